// round 13
// baseline (speedup 1.0000x reference)
#include <cuda_runtime.h>

// InterpolateSparse2d via spatial binning: bin points by 16x16 feature-map tile,
// then one CTA per (batch,tile) loads the 17x17x64 tile into SMEM (NHWC, padded)
// and serves its points entirely from SMEM. No global scratch: DRAM traffic is
// just x (once, +13% halo) and out.
#define BX 16
#define CX 64
#define HXX 240
#define WXX 320
#define NP 20000
#define HW (HXX * WXX)
#define NPT (BX * NP)          // 320000 total points

#define TDIM 16                // tile = 16x16 pixels
#define TILES_X (WXX / TDIM)   // 20
#define TILES_Y (HXX / TDIM)   // 15
#define NTILES (TILES_X * TILES_Y)   // 300
#define NBINS (BX * NTILES)          // 4800

#define TP 17                  // tile + halo
#define NPIX (TP * TP)         // 289
#define PIXSTRIDE 68           // floats per pixel row in smem (64 + pad, 272B, 16B-aligned)
#define SMEM_FLOATS (NPIX * PIXSTRIDE)      // 19652
#define SMEM_BYTES (SMEM_FLOATS * 4)        // 78608

__device__ int g_count[NBINS];
__device__ int g_start[NBINS + 1];
__device__ int g_bin[NPT];
__device__ int g_idx[NPT];

// --------------------------------------------------------------------------
__device__ __forceinline__ void point_cell(
    float px, float py, float Wf, float Hf,
    int& x0, int& y0, float& posx, float& posy)
{
    posx = px * (float)(WXX - 1) / Wf;
    posy = py * (float)(HXX - 1) / Hf;
    x0 = (int)floorf(posx);
    x0 = min(max(x0, 0), WXX - 1);
    y0 = (int)floorf(posy);
    y0 = min(max(y0, 0), HXX - 1);
}

// --------------------------------------------------------------------------
__global__ void zero_counts_kernel() {
    int i = blockIdx.x * blockDim.x + threadIdx.x;
    if (i < NBINS) g_count[i] = 0;
}

// --------------------------------------------------------------------------
__global__ void histogram_kernel(const float* __restrict__ pos,
                                 const int* __restrict__ Hp,
                                 const int* __restrict__ Wp)
{
    int p = blockIdx.x * blockDim.x + threadIdx.x;
    if (p >= NPT) return;
    const float Wf = (float)__ldg(Wp);
    const float Hf = (float)__ldg(Hp);
    int x0, y0; float fx, fy;
    point_cell(__ldg(pos + (size_t)p * 2), __ldg(pos + (size_t)p * 2 + 1),
               Wf, Hf, x0, y0, fx, fy);
    const int b = p / NP;
    const int bin = b * NTILES + (y0 >> 4) * TILES_X + (x0 >> 4);
    g_bin[p] = bin;
    atomicAdd(&g_count[bin], 1);
}

// --------------------------------------------------------------------------
// Single-block exclusive scan over NBINS=4800 (5 bins/thread, 1024 threads).
// Also re-zeros g_count for reuse as scatter cursors.
__global__ void __launch_bounds__(1024) scan_kernel() {
    __shared__ int part[1024];
    const int tid = threadIdx.x;
    const int base = tid * 5;
    int local[5];
    int s = 0;
    #pragma unroll
    for (int k = 0; k < 5; k++) {
        int bidx = base + k;
        local[k] = (bidx < NBINS) ? g_count[bidx] : 0;
        s += local[k];
    }
    part[tid] = s;
    __syncthreads();
    // Hillis-Steele inclusive scan
    for (int off = 1; off < 1024; off <<= 1) {
        int v = (tid >= off) ? part[tid - off] : 0;
        __syncthreads();
        part[tid] += v;
        __syncthreads();
    }
    int excl = part[tid] - s;
    #pragma unroll
    for (int k = 0; k < 5; k++) {
        int bidx = base + k;
        if (bidx < NBINS) {
            g_start[bidx] = excl;
            g_count[bidx] = 0;       // cursor reset
            excl += local[k];
        }
    }
    if (tid == 1023) g_start[NBINS] = part[1023];
}

// --------------------------------------------------------------------------
__global__ void scatter_kernel() {
    int p = blockIdx.x * blockDim.x + threadIdx.x;
    if (p >= NPT) return;
    const int bin = g_bin[p];
    const int off = atomicAdd(&g_count[bin], 1);
    g_idx[g_start[bin] + off] = p;
}

// --------------------------------------------------------------------------
// Main: one CTA per bin. Load 17x17x64 tile NCHW->SMEM NHWC (pixel stride 68),
// then process the bin's points from SMEM.
__global__ void __launch_bounds__(512) interp_tiled_kernel(
    const float* __restrict__ x,
    const float* __restrict__ pos,
    const int* __restrict__ Hp,
    const int* __restrict__ Wp,
    float* __restrict__ out)
{
    extern __shared__ float smem[];

    const int bin = blockIdx.x;
    const int s0  = g_start[bin];
    const int n   = g_start[bin + 1] - s0;
    if (n == 0) return;

    const int b    = bin / NTILES;
    const int t    = bin % NTILES;
    const int ty0  = (t / TILES_X) * TDIM;
    const int tx0  = (t % TILES_X) * TDIM;

    const int tid  = threadIdx.x;
    const int warp = tid >> 5;
    const int lane = tid & 31;

    // ---- load phase: items = (y:17) x (cg:16) x (pxblock:3) = 816 warp-iters
    // lane -> (j = lane&3 channel-in-quad, px = pxblock*8 + lane>>2)
    {
        const int j   = lane & 3;
        const int pxl = lane >> 2;           // 0..7
        const float* xb = x + (size_t)b * CX * HW;
        for (int it = warp; it < 17 * 16 * 3; it += 16) {
            const int y   = it / 48;
            const int rem = it % 48;
            const int cg  = rem / 3;
            const int pb  = rem % 3;
            const int px  = pb * 8 + pxl;
            if (px < TP) {
                const int gy = min(ty0 + y, HXX - 1);
                const int gx = min(tx0 + px, WXX - 1);
                const int c  = cg * 4 + j;
                const float v = __ldg(xb + (size_t)c * HW + gy * WXX + gx);
                smem[(y * TP + px) * PIXSTRIDE + c] = v;
            }
        }
    }
    __syncthreads();

    // ---- gather phase: 16 threads per point (float4 = 4 channels each)
    const int c4   = tid & 15;
    const int slot = tid >> 4;               // 0..31
    const float Wf = (float)__ldg(Wp);
    const float Hf = (float)__ldg(Hp);

    for (int i = slot; i < n; i += 32) {
        const int pid = g_idx[s0 + i];
        const float px = __ldg(pos + (size_t)pid * 2 + 0);
        const float py = __ldg(pos + (size_t)pid * 2 + 1);

        int x0, y0; float posx, posy;
        point_cell(px, py, Wf, Hf, x0, y0, posx, posy);
        const int x1 = min(x0 + 1, WXX - 1);
        const int y1 = min(y0 + 1, HXX - 1);

        const float x0f = (float)x0, x1f = (float)x1;
        const float y0f = (float)y0, y1f = (float)y1;
        const float wa = (x1f - posx) * (y1f - posy);
        const float wb = (x1f - posx) * (posy - y0f);
        const float wc = (posx - x0f) * (y1f - posy);
        const float wd = (posx - x0f) * (posy - y0f);

        const int lx0 = x0 - tx0, lx1 = x1 - tx0;
        const int ly0 = y0 - ty0, ly1 = y1 - ty0;

        const float4 Ia = *(const float4*)&smem[(ly0 * TP + lx0) * PIXSTRIDE + c4 * 4];
        const float4 Ib = *(const float4*)&smem[(ly1 * TP + lx0) * PIXSTRIDE + c4 * 4];
        const float4 Ic = *(const float4*)&smem[(ly0 * TP + lx1) * PIXSTRIDE + c4 * 4];
        const float4 Id = *(const float4*)&smem[(ly1 * TP + lx1) * PIXSTRIDE + c4 * 4];

        float4 r;
        r.x = wa * Ia.x + wb * Ib.x + wc * Ic.x + wd * Id.x;
        r.y = wa * Ia.y + wb * Ib.y + wc * Ic.y + wd * Id.y;
        r.z = wa * Ia.z + wb * Ib.z + wc * Ic.z + wd * Id.z;
        r.w = wa * Ia.w + wb * Ib.w + wc * Ic.w + wd * Id.w;

        __stcs((float4*)(out + (size_t)pid * CX) + c4, r);
    }
}

extern "C" void kernel_launch(void* const* d_in, const int* in_sizes, int n_in,
                              void* d_out, int out_size) {
    const float* x   = (const float*)d_in[0];
    const float* pos = (const float*)d_in[1];
    const int*   Hp  = (const int*)d_in[2];
    const int*   Wp  = (const int*)d_in[3];
    float* out = (float*)d_out;

    static bool attr_set = false;
    if (!attr_set) {
        cudaFuncSetAttribute(interp_tiled_kernel,
                             cudaFuncAttributeMaxDynamicSharedMemorySize,
                             SMEM_BYTES);
        attr_set = true;
    }

    zero_counts_kernel<<<(NBINS + 255) / 256, 256>>>();
    histogram_kernel<<<(NPT + 255) / 256, 256>>>(pos, Hp, Wp);
    scan_kernel<<<1, 1024>>>();
    scatter_kernel<<<(NPT + 255) / 256, 256>>>();
    interp_tiled_kernel<<<NBINS, 512, SMEM_BYTES>>>(x, pos, Hp, Wp, out);
}

// round 14
// speedup vs baseline: 1.5732x; 1.5732x over previous
#include <cuda_runtime.h>

// InterpolateSparse2d: bilinear sampling of x[B,C,Hx,Wx] at pos[B,N,2] -> out[B,N,C]
// Chunked two-phase (R5 structure, tuned): per 4-batch chunk, transpose
// NCHW->NHWC into a single reused 78.6MB scratch (L2-resident), then gather
// from it while hot. x read with __ldcs, out written with __stcs so the
// streaming traffic doesn't evict the scratch. Gather processes 2 points per
// thread (8 independent float4 loads in flight) to cover L2 latency.
#define BX 16
#define CX 64
#define HXX 240
#define WXX 320
#define NP 20000
#define HW (HXX * WXX)     // 76800
#define CHUNK_B 4          // batches per chunk
#define NCHUNK (BX / CHUNK_B)              // 4
#define CHUNK_PTS (CHUNK_B * NP)           // 80000
#define CHUNK_ELEMS ((size_t)CHUNK_B * HW * CX)

// Reused NHWC scratch for one chunk: [CHUNK_B, Hx, Wx, C] = 78.6 MB (fits L2)
__device__ float g_nhwc[CHUNK_ELEMS];

// ---------------------------------------------------------------------------
// Kernel 1: NCHW -> NHWC transpose for one chunk (32x32 smem tiles).
// grid = (HW/32, C/32, CHUNK_B), block = (32, 8).
// ---------------------------------------------------------------------------
__global__ void __launch_bounds__(256) nchw_to_nhwc_chunk_kernel(
    const float* __restrict__ x_chunk)   // x + chunk*CHUNK_B*C*HW
{
    __shared__ float tile[32][33];

    const int b  = blockIdx.z;           // batch within chunk
    const int c0 = blockIdx.y * 32;
    const int s0 = blockIdx.x * 32;      // hw offset

    const float* src = x_chunk + ((size_t)b * CX + c0) * HW + s0;
    #pragma unroll
    for (int i = 0; i < 32; i += 8) {
        tile[threadIdx.y + i][threadIdx.x] =
            __ldcs(src + (size_t)(threadIdx.y + i) * HW + threadIdx.x);
    }
    __syncthreads();

    float* dst = g_nhwc + ((size_t)b * HW + s0) * CX + c0;
    #pragma unroll
    for (int i = 0; i < 32; i += 8) {
        dst[(size_t)(threadIdx.y + i) * CX + threadIdx.x] =
            tile[threadIdx.x][threadIdx.y + i];
    }
}

// ---------------------------------------------------------------------------
// Kernel 2: gather + bilinear blend from L2-hot NHWC scratch.
// block = 256 threads = 16 channel-quads x 16 slots; each slot handles TWO
// points (p and p+16) -> 8 independent float4 L2 loads in flight per thread.
// grid = CHUNK_PTS/32 = 2500.
// ---------------------------------------------------------------------------
__global__ void __launch_bounds__(256) interp_gather_chunk_kernel(
    const float* __restrict__ pos,   // [B, N, 2] (full tensor)
    const int* __restrict__ Hp,
    const int* __restrict__ Wp,
    float* __restrict__ out,         // [B, N, C] (full tensor)
    int point_base)                  // chunk * CHUNK_PTS
{
    const int c4   = threadIdx.x & 15;      // channel quad 0..15
    const int slot = threadIdx.x >> 4;      // 0..15

    const int pl0 = blockIdx.x * 32 + slot; // chunk-local point A
    const int pl1 = pl0 + 16;               // chunk-local point B

    const float Wf = (float)__ldg(Wp);
    const float Hf = (float)__ldg(Hp);
    const float sx = (float)(WXX - 1) / Wf;
    const float sy = (float)(HXX - 1) / Hf;

    const int p0 = point_base + pl0;
    const int p1 = point_base + pl1;

    // pos loads (coalesced: 16 consecutive points per half-warp group)
    const float ax = __ldg(pos + (size_t)p0 * 2 + 0);
    const float ay = __ldg(pos + (size_t)p0 * 2 + 1);
    const float bx = __ldg(pos + (size_t)p1 * 2 + 0);
    const float by = __ldg(pos + (size_t)p1 * 2 + 1);

    // ---- point A indices/weights
    const float posx0 = ax * sx, posy0 = ay * sy;
    int x0a = min(max((int)floorf(posx0), 0), WXX - 1);
    const int x1a = min(x0a + 1, WXX - 1);
    int y0a = min(max((int)floorf(posy0), 0), HXX - 1);
    const int y1a = min(y0a + 1, HXX - 1);
    const float waA = ((float)x1a - posx0) * ((float)y1a - posy0);
    const float wbA = ((float)x1a - posx0) * (posy0 - (float)y0a);
    const float wcA = (posx0 - (float)x0a) * ((float)y1a - posy0);
    const float wdA = (posx0 - (float)x0a) * (posy0 - (float)y0a);

    // ---- point B indices/weights
    const float posx1 = bx * sx, posy1 = by * sy;
    int x0b = min(max((int)floorf(posx1), 0), WXX - 1);
    const int x1b = min(x0b + 1, WXX - 1);
    int y0b = min(max((int)floorf(posy1), 0), HXX - 1);
    const int y1b = min(y0b + 1, HXX - 1);
    const float waB = ((float)x1b - posx1) * ((float)y1b - posy1);
    const float wbB = ((float)x1b - posx1) * (posy1 - (float)y0b);
    const float wcB = (posx1 - (float)x0b) * ((float)y1b - posy1);
    const float wdB = (posx1 - (float)x0b) * (posy1 - (float)y0b);

    const size_t baseA = (size_t)(pl0 / NP) * HW;
    const size_t baseB = (size_t)(pl1 / NP) * HW;

    // ---- issue all 8 loads back-to-back (MLP = 8)
    const float4* aA = (const float4*)(g_nhwc + (baseA + (size_t)y0a * WXX + x0a) * CX) + c4;
    const float4* bA = (const float4*)(g_nhwc + (baseA + (size_t)y1a * WXX + x0a) * CX) + c4;
    const float4* cA = (const float4*)(g_nhwc + (baseA + (size_t)y0a * WXX + x1a) * CX) + c4;
    const float4* dA = (const float4*)(g_nhwc + (baseA + (size_t)y1a * WXX + x1a) * CX) + c4;
    const float4* aB = (const float4*)(g_nhwc + (baseB + (size_t)y0b * WXX + x0b) * CX) + c4;
    const float4* bB = (const float4*)(g_nhwc + (baseB + (size_t)y1b * WXX + x0b) * CX) + c4;
    const float4* cB = (const float4*)(g_nhwc + (baseB + (size_t)y0b * WXX + x1b) * CX) + c4;
    const float4* dB = (const float4*)(g_nhwc + (baseB + (size_t)y1b * WXX + x1b) * CX) + c4;

    const float4 IaA = __ldg(aA);
    const float4 IbA = __ldg(bA);
    const float4 IcA = __ldg(cA);
    const float4 IdA = __ldg(dA);
    const float4 IaB = __ldg(aB);
    const float4 IbB = __ldg(bB);
    const float4 IcB = __ldg(cB);
    const float4 IdB = __ldg(dB);

    float4 rA;
    rA.x = waA * IaA.x + wbA * IbA.x + wcA * IcA.x + wdA * IdA.x;
    rA.y = waA * IaA.y + wbA * IbA.y + wcA * IcA.y + wdA * IdA.y;
    rA.z = waA * IaA.z + wbA * IbA.z + wcA * IcA.z + wdA * IdA.z;
    rA.w = waA * IaA.w + wbA * IbA.w + wcA * IcA.w + wdA * IdA.w;

    float4 rB;
    rB.x = waB * IaB.x + wbB * IbB.x + wcB * IcB.x + wdB * IdB.x;
    rB.y = waB * IaB.y + wbB * IbB.y + wcB * IcB.y + wdB * IdB.y;
    rB.z = waB * IaB.z + wbB * IbB.z + wcB * IcB.z + wdB * IdB.z;
    rB.w = waB * IaB.w + wbB * IbB.w + wcB * IcB.w + wdB * IdB.w;

    __stcs((float4*)(out + (size_t)p0 * CX) + c4, rA);
    __stcs((float4*)(out + (size_t)p1 * CX) + c4, rB);
}

extern "C" void kernel_launch(void* const* d_in, const int* in_sizes, int n_in,
                              void* d_out, int out_size) {
    const float* x   = (const float*)d_in[0];
    const float* pos = (const float*)d_in[1];
    const int*   Hp  = (const int*)d_in[2];
    const int*   Wp  = (const int*)d_in[3];
    float* out = (float*)d_out;

    dim3 tblock(32, 8, 1);
    dim3 tgrid(HW / 32, CX / 32, CHUNK_B);     // (2400, 2, 4)

    dim3 gblock(256, 1, 1);
    dim3 ggrid(CHUNK_PTS / 32, 1, 1);          // 2500 blocks

    for (int chunk = 0; chunk < NCHUNK; chunk++) {
        const float* x_chunk = x + (size_t)chunk * CHUNK_B * CX * HW;
        nchw_to_nhwc_chunk_kernel<<<tgrid, tblock>>>(x_chunk);
        interp_gather_chunk_kernel<<<ggrid, gblock>>>(
            pos, Hp, Wp, out, chunk * CHUNK_PTS);
    }
}